// round 15
// baseline (speedup 1.0000x reference)
#include <cuda_runtime.h>
#include <cuda_fp16.h>
#include <cstdint>

#define DI __device__ __forceinline__

// ---------------- problem constants ----------------
namespace {
constexpr int I_DIM   = 512;
constexpr int O_DIM   = 512;
constexpr int NDEG    = 8;               // degrees 1..8 in the GEMM; d=0 -> bias
constexpr int KTOT    = NDEG * I_DIM;    // 4096, k = i*8 + (d-1)
constexpr int M_DIM   = 16384;
constexpr int M_TILE  = 128;
constexpr int N_TILE  = 64;
constexpr int KBLK    = 64;              // k-tile
constexpr int NKT     = KTOT / KBLK;     // 64
constexpr int STAGES  = 3;
constexpr int THREADS = 256;             // 8 warps: warp_m = wid&3 (32 rows), warp_n = wid>>2 (32 cols)

constexpr float B_SCALE    = 512.0f;
constexpr float B_INVSCALE = 1.0f / 512.0f;

// per stage: A 128 rows x 128B = 16384 ; B 64 rows x 128B = 8192 (both pre-swizzled in gmem)
constexpr int A_STAGE     = 16384;
constexpr int B_STAGE     = 8192;
constexpr int STAGE_BYTES = A_STAGE + B_STAGE;            // 24576
constexpr int MBAR_OFF    = STAGES * STAGE_BYTES;         // 73728; full[s] at +s*16, empty at +s*16+8
constexpr int SMEM_BYTES  = MBAR_OFF + 64 + 1024;         // 74816 -> 3 CTAs/SM

// merged prologue block ranges
constexpr int GEN_BLOCKS  = (M_DIM * I_DIM) / 256;        // 32768
constexpr int PREP_BLOCKS = (I_DIM * O_DIM) / 256;        // 1024
constexpr int BIAS_BLOCKS = (O_DIM * 32) / 256;           // 64
constexpr int PRO_BLOCKS  = GEN_BLOCKS + PREP_BLOCKS + BIAS_BLOCKS;
}

// ---------------- device scratch ----------------
// g_A: tiled [m_tile][k_tile] -> 16384-byte blocks, 128 rows x 128B, SW128-swizzled
// g_B: tiled [k_tile][n_tile] -> 8192-byte blocks, 64 rows x 128B, SW128-swizzled, pre-scaled by 512
__device__ __align__(128) __half g_A[(size_t)M_DIM * KTOT];
__device__ __align__(128) __half g_B[KTOT * O_DIM];
__device__ float g_bias[O_DIM];

// ---------------- helpers ----------------
DI uint32_t smem_u32(const void* p) {
    uint32_t a;
    asm("{ .reg .u64 t; cvta.to.shared.u64 t, %1; cvt.u32.u64 %0, t; }" : "=r"(a) : "l"(p));
    return a;
}
DI uint32_t swz(uint32_t off) { return off ^ ((off >> 3) & 0x70); }   // 128B rows

DI void mbar_init(uint32_t a, uint32_t cnt) {
    asm volatile("mbarrier.init.shared.b64 [%0], %1;" :: "r"(a), "r"(cnt) : "memory");
}
DI void mbar_expect_tx(uint32_t a, uint32_t bytes) {
    asm volatile("mbarrier.arrive.expect_tx.shared.b64 _, [%0], %1;" :: "r"(a), "r"(bytes) : "memory");
}
DI void mbar_arrive(uint32_t a) {
    asm volatile("mbarrier.arrive.shared.b64 _, [%0];" :: "r"(a) : "memory");
}
// suspend-hint wait: HW-sleep in try_wait instead of pure spin
DI void mbar_wait(uint32_t a, uint32_t parity) {
    asm volatile(
        "{\n\t"
        ".reg .pred P;\n\t"
        "WAIT_%=:\n\t"
        "mbarrier.try_wait.parity.shared.b64 P, [%0], %1, 0x989680;\n\t"
        "@P bra DONE_%=;\n\t"
        "bra WAIT_%=;\n\t"
        "DONE_%=:\n\t"
        "}" :: "r"(a), "r"(parity) : "memory");
}
DI void fence_mbar_init() {
    asm volatile("fence.mbarrier_init.release.cluster;" ::: "memory");
}
DI void bulk_g2s(uint32_t dst, const void* src, uint32_t bytes, uint32_t mbar) {
    asm volatile("cp.async.bulk.shared::cluster.global.mbarrier::complete_tx::bytes "
                 "[%0], [%1], %2, [%3];"
                 :: "r"(dst), "l"(src), "r"(bytes), "r"(mbar) : "memory");
}

DI void ldsm_x4(uint32_t& r0, uint32_t& r1, uint32_t& r2, uint32_t& r3, uint32_t addr) {
    asm volatile("ldmatrix.sync.aligned.m8n8.x4.shared.b16 {%0,%1,%2,%3}, [%4];"
                 : "=r"(r0), "=r"(r1), "=r"(r2), "=r"(r3) : "r"(addr));
}
DI void ldsm_x4_t(uint32_t& r0, uint32_t& r1, uint32_t& r2, uint32_t& r3, uint32_t addr) {
    asm volatile("ldmatrix.sync.aligned.m8n8.x4.trans.shared.b16 {%0,%1,%2,%3}, [%4];"
                 : "=r"(r0), "=r"(r1), "=r"(r2), "=r"(r3) : "r"(addr));
}
DI void mma16816(float& c0, float& c1, float& c2, float& c3,
                 uint32_t a0, uint32_t a1, uint32_t a2, uint32_t a3,
                 uint32_t b0, uint32_t b1) {
    asm volatile("mma.sync.aligned.m16n8k16.row.col.f32.f16.f16.f32 "
                 "{%0,%1,%2,%3}, {%4,%5,%6,%7}, {%8,%9}, {%0,%1,%2,%3};"
                 : "+f"(c0), "+f"(c1), "+f"(c2), "+f"(c3)
                 : "r"(a0), "r"(a1), "r"(a2), "r"(a3), "r"(b0), "r"(b1));
}

// tanh via ex2/rcp: abs err ~1e-6, << fp16 feature quantization
DI float fast_tanh(float v) {
    float f = fminf(fmaxf(v, -15.f), 15.f) * 2.8853900817779268f; // 2*log2(e)
    float e; asm("ex2.approx.f32 %0, %1;" : "=f"(e) : "f"(f));
    float r; asm("rcp.approx.f32 %0, %1;" : "=f"(r) : "f"(e + 1.f));
    return (e - 1.f) * r;
}

// ---------------- merged prologue: gen A + repack B + bias, one launch ----------------
// C layout: C[i][n][d], 9 floats per (i,n). Writes TILED, PRE-SWIZZLED layouts.
__global__ void __launch_bounds__(256) prologue_kernel(const float* __restrict__ x,
                                                       const float* __restrict__ C) {
    const int b = blockIdx.x;
    if (b < GEN_BLOCKS) {
        // gen: one thread per (m, i): tanh + Legendre -> 8 fp16, one swizzled 16B store
        int tid = b * 256 + threadIdx.x;
        float t = fast_tanh(x[tid]);                    // x is [m][i] contiguous
        int i = tid & (I_DIM - 1);
        int m = tid >> 9;
        float pm2 = 1.f, pm1 = t;
        __half h[8];
        h[0] = __float2half_rn(t);
        #pragma unroll
        for (int d = 2; d <= NDEG; d++) {
            const float c1 = (2.f * d - 1.f) / (float)d;
            const float c2 = (d - 1.f) / (float)d;
            float pc = c1 * t * pm1 - c2 * pm2;
            pm2 = pm1; pm1 = pc;
            h[d - 1] = __float2half_rn(pc);
        }
        uint4 v;
        v.x = *reinterpret_cast<uint32_t*>(&h[0]);
        v.y = *reinterpret_cast<uint32_t*>(&h[2]);
        v.z = *reinterpret_cast<uint32_t*>(&h[4]);
        v.w = *reinterpret_cast<uint32_t*>(&h[6]);
        // tiled: tile (mt, kt) = mt*64+kt; within: row mr, 16B chunk c=i&7
        int mt = m >> 7, mr = m & 127, kt = i >> 3, c = i & 7;
        char* dst = (char*)g_A + ((size_t)(mt * 64 + kt) << 14)
                  + swz((uint32_t)mr * 128 + c * 16);
        *reinterpret_cast<uint4*>(dst) = v;
    } else if (b < GEN_BLOCKS + PREP_BLOCKS) {
        // repack B: one thread per (i, n) -> 8 swizzled 2B stores into tile (kt, nt)
        int tid = (b - GEN_BLOCKS) * 256 + threadIdx.x;
        int n = tid & (O_DIM - 1);
        int i = tid >> 9;
        const float* src = C + ((size_t)i * O_DIM + n) * 9;
        int kt = i >> 3, nt = n >> 6, nl = n & 63, klb = (i & 7) * 8;
        char* base = (char*)g_B + ((size_t)(kt * 8 + nt) << 13);
        #pragma unroll
        for (int d0 = 0; d0 < 8; d0++) {
            __half hv = __float2half_rn(src[d0 + 1] * B_SCALE);
            *reinterpret_cast<__half*>(base + swz((uint32_t)(klb + d0) * 128 + nl * 2)) = hv;
        }
    } else {
        // bias[n] = sum_i C[i][n][0]
        int tid = (b - GEN_BLOCKS - PREP_BLOCKS) * 256 + threadIdx.x;
        int gw  = tid >> 5;
        int lid = threadIdx.x & 31;
        float s = 0.f;
        for (int i = lid; i < I_DIM; i += 32)
            s += C[((size_t)i * O_DIM + gw) * 9];
        #pragma unroll
        for (int o = 16; o; o >>= 1) s += __shfl_xor_sync(0xffffffffu, s, o);
        if (lid == 0) g_bias[gw] = s;
    }
}

// ---------------- GEMM: TMA bulk loads + mbarrier ring, ROTATING producer warp ----------------
__global__ void __launch_bounds__(THREADS, 3)
gemm_main(float* __restrict__ out) {
    extern __shared__ char smem_raw[];
    const uint32_t sb = (smem_u32(smem_raw) + 1023u) & ~1023u;

    const int tid = threadIdx.x;
    const int lid = tid & 31;
    const int wid = tid >> 5;
    const int warp_m = wid & 3;           // 32-row slab
    const int warp_n = wid >> 2;          // 0..1 -> 32-col slab
    const int nt = blockIdx.x;            // n-tile index, x fastest: 8 N-CTAs share A tiles in L2
    const int n0 = nt * N_TILE;
    const int mt = blockIdx.y;
    const int r0 = mt * M_TILE;

    const int la_row = lid & 15;
    const int la_hi  = lid >> 4;

    // gmem tile bases (tile-contiguous, pre-swizzled)
    const char* gA = (const char*)g_A + ((size_t)(mt * 64) << 14);    // + t*16384
    const char* gB = (const char*)g_B + ((size_t)nt << 13);           // + t*8*8192

    const uint32_t mb = sb + MBAR_OFF;
    auto full_bar  = [&](int s) { return mb + (uint32_t)s * 16; };
    auto empty_bar = [&](int s) { return mb + (uint32_t)s * 16 + 8; };

    if (tid == 0) {
        #pragma unroll
        for (int s = 0; s < STAGES; s++) {
            mbar_init(full_bar(s), 1);     // completed by expect_tx arrival + tx bytes
            mbar_init(empty_bar(s), 8);    // one arrive per warp
        }
        fence_mbar_init();
    }
    __syncthreads();

    // prime 3 stages
    if (tid == 0) {
        #pragma unroll
        for (int tp = 0; tp < STAGES; tp++) {
            const uint32_t stg = sb + (uint32_t)tp * STAGE_BYTES;
            mbar_expect_tx(full_bar(tp), STAGE_BYTES);
            bulk_g2s(stg,            gA + (size_t)tp * 16384, A_STAGE, full_bar(tp));
            bulk_g2s(stg + A_STAGE,  gB + (size_t)tp * 8 * 8192, B_STAGE, full_bar(tp));
        }
    }

    float acc[2][4][4];
    #pragma unroll
    for (int a = 0; a < 2; a++)
        #pragma unroll
        for (int b = 0; b < 4; b++)
            #pragma unroll
            for (int c = 0; c < 4; c++) acc[a][b][c] = 0.f;

    // hoisted per-warp constants
    const uint32_t a_off0 = (uint32_t)(warp_m * 32 + la_row) * 128 + la_hi * 16;
    const uint32_t b_off0 = (uint32_t)la_row * 128 + (warp_n * 32 + la_hi * 8) * 2;

    for (int t = 0; t < NKT; t++) {
        const int s = t % STAGES;
        const uint32_t ph = (uint32_t)(t / STAGES) & 1u;

        mbar_wait(full_bar(s), ph);        // per-warp wait: warps decouple

        const uint32_t Abase = sb + (uint32_t)s * STAGE_BYTES;
        const uint32_t Bbase = Abase + A_STAGE;

        #pragma unroll
        for (int j = 0; j < 4; j++) {      // k16 steps
            uint32_t a0[4], a1[4];
            {
                uint32_t off0 = a_off0 + j * 32;
                ldsm_x4(a0[0], a0[1], a0[2], a0[3], Abase + swz(off0));
                ldsm_x4(a1[0], a1[1], a1[2], a1[3], Abase + swz(off0 + 16 * 128));
            }
            #pragma unroll
            for (int nb = 0; nb < 2; nb++) {
                uint32_t b0, b1, b2, b3;
                uint32_t boff = b_off0 + (uint32_t)j * 16 * 128 + nb * 32;
                ldsm_x4_t(b0, b1, b2, b3, Bbase + swz(boff));
                float* c00 = acc[0][2 * nb];
                float* c01 = acc[0][2 * nb + 1];
                float* c10 = acc[1][2 * nb];
                float* c11 = acc[1][2 * nb + 1];
                mma16816(c00[0], c00[1], c00[2], c00[3], a0[0], a0[1], a0[2], a0[3], b0, b1);
                mma16816(c01[0], c01[1], c01[2], c01[3], a0[0], a0[1], a0[2], a0[3], b2, b3);
                mma16816(c10[0], c10[1], c10[2], c10[3], a1[0], a1[1], a1[2], a1[3], b0, b1);
                mma16816(c11[0], c11[1], c11[2], c11[3], a1[0], a1[1], a1[2], a1[3], b2, b3);
            }
        }

        if (lid == 0) {
            mbar_arrive(empty_bar(s));     // this warp done with stage s
            // rotating producer: warp (t&7) refills stage s for tile t+3
            if (wid == (t & 7)) {
                const int tp = t + STAGES;
                if (tp < NKT) {
                    mbar_wait(empty_bar(s), ph);   // all 8 warps consumed tile t
                    const uint32_t stg = sb + (uint32_t)s * STAGE_BYTES;
                    mbar_expect_tx(full_bar(s), STAGE_BYTES);
                    bulk_g2s(stg,           gA + (size_t)tp * 16384, A_STAGE, full_bar(s));
                    bulk_g2s(stg + A_STAGE, gB + (size_t)tp * 8 * 8192, B_STAGE, full_bar(s));
                }
            }
        }
    }

    // ---- epilogue: unscale, add d=0 bias, store fp32 (per-warp, no sync needed) ----
    {
        const int g  = lid >> 2;
        const int tg = lid & 3;
        #pragma unroll
        for (int mt2 = 0; mt2 < 2; mt2++) {
            const int rbase = r0 + warp_m * 32 + mt2 * 16 + g;
            #pragma unroll
            for (int ntl = 0; ntl < 4; ntl++) {
                const int col = n0 + warp_n * 32 + ntl * 8 + tg * 2;
                const float bz0 = g_bias[col];
                const float bz1 = g_bias[col + 1];
                float2 v;
                v.x = acc[mt2][ntl][0] * B_INVSCALE + bz0;
                v.y = acc[mt2][ntl][1] * B_INVSCALE + bz1;
                *reinterpret_cast<float2*>(out + (size_t)rbase * O_DIM + col) = v;
                v.x = acc[mt2][ntl][2] * B_INVSCALE + bz0;
                v.y = acc[mt2][ntl][3] * B_INVSCALE + bz1;
                *reinterpret_cast<float2*>(out + (size_t)(rbase + 8) * O_DIM + col) = v;
            }
        }
    }
}

// ---------------- launch ----------------
extern "C" void kernel_launch(void* const* d_in, const int* in_sizes, int n_in,
                              void* d_out, int out_size) {
    const float* x = (const float*)d_in[0];
    const float* C = (const float*)d_in[1];
    float* out = (float*)d_out;

    prologue_kernel<<<PRO_BLOCKS, 256>>>(x, C);

    cudaFuncSetAttribute(gemm_main, cudaFuncAttributeMaxDynamicSharedMemorySize, SMEM_BYTES);
    dim3 grid(O_DIM / N_TILE, M_DIM / M_TILE);   // (8, 128), n fastest
    gemm_main<<<grid, THREADS, SMEM_BYTES>>>(out);
}

// round 16
// speedup vs baseline: 1.0664x; 1.0664x over previous
#include <cuda_runtime.h>
#include <cuda_fp16.h>
#include <cstdint>

#define DI __device__ __forceinline__

// ---------------- problem constants ----------------
namespace {
constexpr int I_DIM   = 512;
constexpr int O_DIM   = 512;
constexpr int NDEG    = 8;               // degrees 1..8 in the GEMM; d=0 -> bias
constexpr int KTOT    = NDEG * I_DIM;    // 4096, k = i*8 + (d-1)
constexpr int M_DIM   = 16384;
constexpr int M_TILE  = 128;
constexpr int N_TILE  = 64;
constexpr int KBLK    = 64;              // k-tile
constexpr int NKT     = KTOT / KBLK;     // 64
constexpr int STAGES  = 3;
constexpr int THREADS = 288;             // 8 consumer warps + 1 producer warp

constexpr float B_SCALE    = 512.0f;
constexpr float B_INVSCALE = 1.0f / 512.0f;

// per stage: A 128 rows x 128B = 16384 ; B 64 rows x 128B = 8192 (both pre-swizzled in gmem)
constexpr int A_STAGE     = 16384;
constexpr int B_STAGE     = 8192;
constexpr int STAGE_BYTES = A_STAGE + B_STAGE;            // 24576
constexpr int MBAR_OFF    = STAGES * STAGE_BYTES;         // 73728; full[s] at +s*16, empty at +s*16+8
constexpr int SMEM_BYTES  = MBAR_OFF + 64 + 1024;         // 74816 -> 3 CTAs/SM

// merged prologue block ranges
constexpr int GEN_BLOCKS  = (M_DIM * I_DIM) / 256;        // 32768
constexpr int PREP_BLOCKS = (I_DIM * O_DIM) / 256;        // 1024
constexpr int BIAS_BLOCKS = (O_DIM * 32) / 256;           // 64
constexpr int PRO_BLOCKS  = GEN_BLOCKS + PREP_BLOCKS + BIAS_BLOCKS;
}

// ---------------- device scratch ----------------
// g_A: tiled [m_tile][k_tile] -> 16384-byte blocks, 128 rows x 128B, SW128-swizzled
// g_B: tiled [k_tile][n_tile] -> 8192-byte blocks, 64 rows x 128B, SW128-swizzled, pre-scaled by 512
__device__ __align__(128) __half g_A[(size_t)M_DIM * KTOT];
__device__ __align__(128) __half g_B[KTOT * O_DIM];
__device__ float g_bias[O_DIM];

// ---------------- helpers ----------------
DI uint32_t smem_u32(const void* p) {
    uint32_t a;
    asm("{ .reg .u64 t; cvta.to.shared.u64 t, %1; cvt.u32.u64 %0, t; }" : "=r"(a) : "l"(p));
    return a;
}
DI uint32_t swz(uint32_t off) { return off ^ ((off >> 3) & 0x70); }   // 128B rows

DI void mbar_init(uint32_t a, uint32_t cnt) {
    asm volatile("mbarrier.init.shared.b64 [%0], %1;" :: "r"(a), "r"(cnt) : "memory");
}
DI void mbar_expect_tx(uint32_t a, uint32_t bytes) {
    asm volatile("mbarrier.arrive.expect_tx.shared.b64 _, [%0], %1;" :: "r"(a), "r"(bytes) : "memory");
}
DI void mbar_arrive(uint32_t a) {
    asm volatile("mbarrier.arrive.shared.b64 _, [%0];" :: "r"(a) : "memory");
}
DI void mbar_wait(uint32_t a, uint32_t parity) {
    asm volatile(
        "{\n\t"
        ".reg .pred P;\n\t"
        "WAIT_%=:\n\t"
        "mbarrier.try_wait.parity.shared.b64 P, [%0], %1, 0x989680;\n\t"
        "@P bra DONE_%=;\n\t"
        "bra WAIT_%=;\n\t"
        "DONE_%=:\n\t"
        "}" :: "r"(a), "r"(parity) : "memory");
}
DI void fence_mbar_init() {
    asm volatile("fence.mbarrier_init.release.cluster;" ::: "memory");
}
DI void bulk_g2s(uint32_t dst, const void* src, uint32_t bytes, uint32_t mbar) {
    asm volatile("cp.async.bulk.shared::cluster.global.mbarrier::complete_tx::bytes "
                 "[%0], [%1], %2, [%3];"
                 :: "r"(dst), "l"(src), "r"(bytes), "r"(mbar) : "memory");
}

DI void ldsm_x4(uint32_t& r0, uint32_t& r1, uint32_t& r2, uint32_t& r3, uint32_t addr) {
    asm volatile("ldmatrix.sync.aligned.m8n8.x4.shared.b16 {%0,%1,%2,%3}, [%4];"
                 : "=r"(r0), "=r"(r1), "=r"(r2), "=r"(r3) : "r"(addr));
}
DI void ldsm_x4_t(uint32_t& r0, uint32_t& r1, uint32_t& r2, uint32_t& r3, uint32_t addr) {
    asm volatile("ldmatrix.sync.aligned.m8n8.x4.trans.shared.b16 {%0,%1,%2,%3}, [%4];"
                 : "=r"(r0), "=r"(r1), "=r"(r2), "=r"(r3) : "r"(addr));
}
DI void mma16816(float& c0, float& c1, float& c2, float& c3,
                 uint32_t a0, uint32_t a1, uint32_t a2, uint32_t a3,
                 uint32_t b0, uint32_t b1) {
    asm volatile("mma.sync.aligned.m16n8k16.row.col.f32.f16.f16.f32 "
                 "{%0,%1,%2,%3}, {%4,%5,%6,%7}, {%8,%9}, {%0,%1,%2,%3};"
                 : "+f"(c0), "+f"(c1), "+f"(c2), "+f"(c3)
                 : "r"(a0), "r"(a1), "r"(a2), "r"(a3), "r"(b0), "r"(b1));
}

// tanh via ex2/rcp: abs err ~1e-6, << fp16 feature quantization
DI float fast_tanh(float v) {
    float f = fminf(fmaxf(v, -15.f), 15.f) * 2.8853900817779268f; // 2*log2(e)
    float e; asm("ex2.approx.f32 %0, %1;" : "=f"(e) : "f"(f));
    float r; asm("rcp.approx.f32 %0, %1;" : "=f"(r) : "f"(e + 1.f));
    return (e - 1.f) * r;
}

// ---------------- merged prologue: gen A + repack B + bias, one launch ----------------
// C layout: C[i][n][d], 9 floats per (i,n). Writes TILED, PRE-SWIZZLED layouts.
__global__ void __launch_bounds__(256) prologue_kernel(const float* __restrict__ x,
                                                       const float* __restrict__ C) {
    const int b = blockIdx.x;
    if (b < GEN_BLOCKS) {
        // gen: one thread per (m, i): tanh + Legendre -> 8 fp16, one swizzled 16B store
        int tid = b * 256 + threadIdx.x;
        float t = fast_tanh(x[tid]);                    // x is [m][i] contiguous
        int i = tid & (I_DIM - 1);
        int m = tid >> 9;
        float pm2 = 1.f, pm1 = t;
        __half h[8];
        h[0] = __float2half_rn(t);
        #pragma unroll
        for (int d = 2; d <= NDEG; d++) {
            const float c1 = (2.f * d - 1.f) / (float)d;
            const float c2 = (d - 1.f) / (float)d;
            float pc = c1 * t * pm1 - c2 * pm2;
            pm2 = pm1; pm1 = pc;
            h[d - 1] = __float2half_rn(pc);
        }
        uint4 v;
        v.x = *reinterpret_cast<uint32_t*>(&h[0]);
        v.y = *reinterpret_cast<uint32_t*>(&h[2]);
        v.z = *reinterpret_cast<uint32_t*>(&h[4]);
        v.w = *reinterpret_cast<uint32_t*>(&h[6]);
        // tiled: tile (mt, kt) = mt*64+kt; within: row mr, 16B chunk c=i&7
        int mt = m >> 7, mr = m & 127, kt = i >> 3, c = i & 7;
        char* dst = (char*)g_A + ((size_t)(mt * 64 + kt) << 14)
                  + swz((uint32_t)mr * 128 + c * 16);
        *reinterpret_cast<uint4*>(dst) = v;
    } else if (b < GEN_BLOCKS + PREP_BLOCKS) {
        // repack B: one thread per (i, n) -> 8 swizzled 2B stores into tile (kt, nt)
        int tid = (b - GEN_BLOCKS) * 256 + threadIdx.x;
        int n = tid & (O_DIM - 1);
        int i = tid >> 9;
        const float* src = C + ((size_t)i * O_DIM + n) * 9;
        int kt = i >> 3, nt = n >> 6, nl = n & 63, klb = (i & 7) * 8;
        char* base = (char*)g_B + ((size_t)(kt * 8 + nt) << 13);
        #pragma unroll
        for (int d0 = 0; d0 < 8; d0++) {
            __half hv = __float2half_rn(src[d0 + 1] * B_SCALE);
            *reinterpret_cast<__half*>(base + swz((uint32_t)(klb + d0) * 128 + nl * 2)) = hv;
        }
    } else {
        // bias[n] = sum_i C[i][n][0]
        int tid = (b - GEN_BLOCKS - PREP_BLOCKS) * 256 + threadIdx.x;
        int gw  = tid >> 5;
        int lid = threadIdx.x & 31;
        float s = 0.f;
        for (int i = lid; i < I_DIM; i += 32)
            s += C[((size_t)i * O_DIM + gw) * 9];
        #pragma unroll
        for (int o = 16; o; o >>= 1) s += __shfl_xor_sync(0xffffffffu, s, o);
        if (lid == 0) g_bias[gw] = s;
    }
}

// ---------------- GEMM: warp-specialized producer (warp 8) + 8 consumer warps ----------------
__global__ void __launch_bounds__(THREADS, 3)
gemm_main(float* __restrict__ out) {
    extern __shared__ char smem_raw[];
    const uint32_t sb = (smem_u32(smem_raw) + 1023u) & ~1023u;

    const int tid = threadIdx.x;
    const int lid = tid & 31;
    const int wid = tid >> 5;
    const int nt = blockIdx.x;            // n-tile index, x fastest: 8 N-CTAs share A tiles in L2
    const int n0 = nt * N_TILE;
    const int mt = blockIdx.y;
    const int r0 = mt * M_TILE;

    const uint32_t mb = sb + MBAR_OFF;
    auto full_bar  = [&](int s) { return mb + (uint32_t)s * 16; };
    auto empty_bar = [&](int s) { return mb + (uint32_t)s * 16 + 8; };

    if (tid == 0) {
        #pragma unroll
        for (int s = 0; s < STAGES; s++) {
            mbar_init(full_bar(s), 1);     // completed by expect_tx arrival + tx bytes
            mbar_init(empty_bar(s), 8);    // one arrive per consumer warp
        }
        fence_mbar_init();
    }
    __syncthreads();

    if (wid == 8) {
        // ---------------- producer warp: issue all NKT tile loads ----------------
        if (lid == 0) {
            const char* gA = (const char*)g_A + ((size_t)(mt * 64) << 14);
            const char* gB = (const char*)g_B + ((size_t)nt << 13);
            for (int tp = 0; tp < NKT; tp++) {
                const int s = tp % STAGES;
                if (tp >= STAGES)
                    mbar_wait(empty_bar(s), (uint32_t)((tp / STAGES) - 1) & 1u);
                const uint32_t stg = sb + (uint32_t)s * STAGE_BYTES;
                mbar_expect_tx(full_bar(s), STAGE_BYTES);
                bulk_g2s(stg,           gA + (size_t)tp * 16384,    A_STAGE, full_bar(s));
                bulk_g2s(stg + A_STAGE, gB + (size_t)tp * 8 * 8192, B_STAGE, full_bar(s));
            }
        }
        return;                            // producer exits; no further CTA-wide syncs
    }

    // ---------------- consumer warps (wid 0..7) ----------------
    const int warp_m = wid & 3;            // 32-row slab
    const int warp_n = wid >> 2;           // 0..1 -> 32-col slab
    const int la_row = lid & 15;
    const int la_hi  = lid >> 4;

    float acc[2][4][4];
    #pragma unroll
    for (int a = 0; a < 2; a++)
        #pragma unroll
        for (int b = 0; b < 4; b++)
            #pragma unroll
            for (int c = 0; c < 4; c++) acc[a][b][c] = 0.f;

    const uint32_t a_off0 = (uint32_t)(warp_m * 32 + la_row) * 128 + la_hi * 16;
    const uint32_t b_off0 = (uint32_t)la_row * 128 + (warp_n * 32 + la_hi * 8) * 2;

    for (int t = 0; t < NKT; t++) {
        const int s = t % STAGES;
        const uint32_t ph = (uint32_t)(t / STAGES) & 1u;

        mbar_wait(full_bar(s), ph);        // per-warp wait: warps decouple

        const uint32_t Abase = sb + (uint32_t)s * STAGE_BYTES;
        const uint32_t Bbase = Abase + A_STAGE;

        #pragma unroll
        for (int j = 0; j < 4; j++) {      // k16 steps
            uint32_t a0[4], a1[4];
            {
                uint32_t off0 = a_off0 + j * 32;
                ldsm_x4(a0[0], a0[1], a0[2], a0[3], Abase + swz(off0));
                ldsm_x4(a1[0], a1[1], a1[2], a1[3], Abase + swz(off0 + 16 * 128));
            }
            #pragma unroll
            for (int nb = 0; nb < 2; nb++) {
                uint32_t b0, b1, b2, b3;
                uint32_t boff = b_off0 + (uint32_t)j * 16 * 128 + nb * 32;
                ldsm_x4_t(b0, b1, b2, b3, Bbase + swz(boff));
                float* c00 = acc[0][2 * nb];
                float* c01 = acc[0][2 * nb + 1];
                float* c10 = acc[1][2 * nb];
                float* c11 = acc[1][2 * nb + 1];
                mma16816(c00[0], c00[1], c00[2], c00[3], a0[0], a0[1], a0[2], a0[3], b0, b1);
                mma16816(c01[0], c01[1], c01[2], c01[3], a0[0], a0[1], a0[2], a0[3], b2, b3);
                mma16816(c10[0], c10[1], c10[2], c10[3], a1[0], a1[1], a1[2], a1[3], b0, b1);
                mma16816(c11[0], c11[1], c11[2], c11[3], a1[0], a1[1], a1[2], a1[3], b2, b3);
            }
        }

        if (lid == 0) mbar_arrive(empty_bar(s));   // this warp done with stage s
    }

    // ---- epilogue: unscale, add d=0 bias, store fp32 (per-warp, no sync needed) ----
    {
        const int g  = lid >> 2;
        const int tg = lid & 3;
        #pragma unroll
        for (int mt2 = 0; mt2 < 2; mt2++) {
            const int rbase = r0 + warp_m * 32 + mt2 * 16 + g;
            #pragma unroll
            for (int ntl = 0; ntl < 4; ntl++) {
                const int col = n0 + warp_n * 32 + ntl * 8 + tg * 2;
                const float bz0 = g_bias[col];
                const float bz1 = g_bias[col + 1];
                float2 v;
                v.x = acc[mt2][ntl][0] * B_INVSCALE + bz0;
                v.y = acc[mt2][ntl][1] * B_INVSCALE + bz1;
                *reinterpret_cast<float2*>(out + (size_t)rbase * O_DIM + col) = v;
                v.x = acc[mt2][ntl][2] * B_INVSCALE + bz0;
                v.y = acc[mt2][ntl][3] * B_INVSCALE + bz1;
                *reinterpret_cast<float2*>(out + (size_t)(rbase + 8) * O_DIM + col) = v;
            }
        }
    }
}

// ---------------- launch ----------------
extern "C" void kernel_launch(void* const* d_in, const int* in_sizes, int n_in,
                              void* d_out, int out_size) {
    const float* x = (const float*)d_in[0];
    const float* C = (const float*)d_in[1];
    float* out = (float*)d_out;

    prologue_kernel<<<PRO_BLOCKS, 256>>>(x, C);

    cudaFuncSetAttribute(gemm_main, cudaFuncAttributeMaxDynamicSharedMemorySize, SMEM_BYTES);
    dim3 grid(O_DIM / N_TILE, M_DIM / M_TILE);   // (8, 128), n fastest
    gemm_main<<<grid, THREADS, SMEM_BYTES>>>(out);
}